// round 7
// baseline (speedup 1.0000x reference)
#include <cuda_runtime.h>

// CapsNet dynamic routing, factorized. One 1024-thread CTA = two independent
// 512-thread halves (one batch each), synced by named barriers (ids 1,2) so
// the halves' phases interleave and hide each other's barrier/tail stalls.

namespace {
constexpr int O_ = 10, U_ = 36, E_ = 16, F_ = 8;
constexpr int N_ = 1152;
constexpr int B_ = 256;
constexpr int BT = 2;
constexpr int T_ = 1024;
constexpr int NP = 1157;             // c plane stride

// shared layout (floats)
constexpr int OFF_XS = 0;                      // x [BT][N][F] swizzled   18432
constexpr int OFF_C  = OFF_XS + BT * N_ * F_;  // c 2 halves x 10*NP      23140
constexpr int OFF_P  = OFF_C + 2 * 10 * NP;    // pb 2 halves x 1440 f4   11520
constexpr int OFF_VV = OFF_P + 11520;          // vv 2 x 160                320
constexpr int SM_FLOATS = OFF_VV + 320;        // 53412 -> 213,648 B
} // namespace

__device__ __forceinline__ int xsw(int i) { return i ^ ((i >> 3) & 7); }

__global__ __launch_bounds__(T_, 1)
void caps_route_kernel(const float* __restrict__ x,
                       const float* __restrict__ Wg,
                       float* __restrict__ out) {
    extern __shared__ float sm[];
    const int tid = threadIdx.x;
    const int h = tid >> 9;          // half id (batch within pair)
    const int t = tid & 511;         // thread id within half
    const int b0 = blockIdx.x * BT;

    float4* xs4 = reinterpret_cast<float4*>(sm + OFF_XS);
    float* cc   = sm + OFF_C + h * (10 * NP);
    float4* pb4 = reinterpret_cast<float4*>(sm + OFF_P) + h * 1440;
    float* vv   = sm + OFF_VV + h * 160;
    const float4* __restrict__ wp4 = reinterpret_cast<const float4*>(Wg);

    // ---- global init: x tiles (coalesced, swizzled), c = 1/O ----
    {
        const float4* xg = reinterpret_cast<const float4*>(x) + (size_t)b0 * (N_ * F_ / 4);
        #pragma unroll
        for (int i = tid; i < BT * N_ * F_ / 4; i += T_) xs4[xsw(i)] = xg[i];
    }
    for (int i = tid; i < 2 * 10 * NP; i += T_) sm[OFF_C + i] = 0.1f;
    __syncthreads();

    // half-scoped barrier
    const int barid = h + 1;
#define BARH() asm volatile("bar.sync %0, 512;" :: "r"(barid) : "memory")

    // P2 decode (288 tasks): t = u<<3 | oh<<2 | fg<<1 | sh
    const int p2_u  = t >> 3;
    const int p2_oh = (t >> 2) & 1;
    const int p2_fg = (t >> 1) & 1;
    const int p2_sh = t & 1;
    const float* p2_cb = cc + p2_oh * 5 * NP + p2_u * 32 + p2_sh * 16;
    const int p2_pbase = (h * N_ + p2_u * 32 + p2_sh * 16) * 2 + p2_fg;
    float4* p2_pr = pb4 + t * 5;

    // P3 decode: warp w (0..15) owns o=w (<10); lanes = (e low4, ch bit4)
    const int w = t >> 5;
    const int lane = t & 31;
    const int p3_e  = lane & 15;
    const int p3_ch = lane >> 4;
    const int p3_oh = (w >= 5);
    const int p3_k  = w - 5 * p3_oh;

    for (int it = 0; it < 4; ++it) {
        // ---- P2: y partials for (u,fg,oh,sh); 5 o-accumulators ----
        if (t < 288) {
            float4 a0 = make_float4(0.f,0.f,0.f,0.f), a1 = a0, a2 = a0, a3 = a0, a4 = a0;
            #pragma unroll
            for (int j = 0; j < 16; ++j) {
                const int s = (p2_u + j) & 15;
                const float4 xv = xs4[xsw(p2_pbase + 2 * s)];
                const float c0 = p2_cb[s];
                const float c1 = p2_cb[NP + s];
                const float c2 = p2_cb[2 * NP + s];
                const float c3 = p2_cb[3 * NP + s];
                const float c4 = p2_cb[4 * NP + s];
                a0.x += c0 * xv.x; a0.y += c0 * xv.y; a0.z += c0 * xv.z; a0.w += c0 * xv.w;
                a1.x += c1 * xv.x; a1.y += c1 * xv.y; a1.z += c1 * xv.z; a1.w += c1 * xv.w;
                a2.x += c2 * xv.x; a2.y += c2 * xv.y; a2.z += c2 * xv.z; a2.w += c2 * xv.w;
                a3.x += c3 * xv.x; a3.y += c3 * xv.y; a3.z += c3 * xv.z; a3.w += c3 * xv.w;
                a4.x += c4 * xv.x; a4.y += c4 * xv.y; a4.z += c4 * xv.z; a4.w += c4 * xv.w;
            }
            p2_pr[0] = a0; p2_pr[1] = a1; p2_pr[2] = a2; p2_pr[3] = a3; p2_pr[4] = a4;
        }
        BARH();

        // ---- P3 (+fused squash): warp o; lane (e, ch of 18 u) -> vv ----
        if (w < 10) {
            float p = 0.f;
            #pragma unroll 6
            for (int jj = 0; jj < 18; ++jj) {
                const int u = p3_ch * 18 + jj;
                const int rb = ((u << 3) | (p3_oh << 2)) * 5 + p3_k;
                float4 A0 = pb4[rb];                // fg0 sh0
                const float4 t0 = pb4[rb + 5];      // fg0 sh1
                float4 A1 = pb4[rb + 10];           // fg1 sh0
                const float4 t1 = pb4[rb + 15];     // fg1 sh1
                A0.x += t0.x; A0.y += t0.y; A0.z += t0.z; A0.w += t0.w;
                A1.x += t1.x; A1.y += t1.y; A1.z += t1.z; A1.w += t1.w;
                const int wb = ((w * U_ + u) * E_ + p3_e) * 2;
                const float4 w0 = wp4[wb];
                const float4 w1 = wp4[wb + 1];
                p += w0.x * A0.x + w0.y * A0.y + w0.z * A0.z + w0.w * A0.w
                   + w1.x * A1.x + w1.y * A1.y + w1.z * A1.z + w1.w * A1.w;
            }
            const float s = p + __shfl_xor_sync(0xffffffffu, p, 16);
            float nsq = s * s;
            #pragma unroll
            for (int m = 1; m <= 8; m <<= 1)
                nsq += __shfl_xor_sync(0xffffffffu, nsq, m);
            const float sc = sqrtf(nsq) / (1.f + nsq);
            if (p3_ch == 0) vv[w * 16 + p3_e] = s * sc;
        }
        BARH();

        if (it == 3) break;

        // ---- P5: wv[o,u] (both fg) into pb front ----
        if (t < 360) {
            const int o = t / 36, u = t - o * 36;
            const float4* wp = wp4 + (o * U_ + u) * E_ * 2;
            const float* v0 = vv + o * 16;
            float4 A = make_float4(0.f,0.f,0.f,0.f);
            float4 Bv = A;
            #pragma unroll
            for (int e = 0; e < E_; ++e) {
                const float4 w0 = wp[e * 2];
                const float4 w1 = wp[e * 2 + 1];
                const float ve = v0[e];
                A.x  += ve * w0.x; A.y  += ve * w0.y; A.z  += ve * w0.z; A.w  += ve * w0.w;
                Bv.x += ve * w1.x; Bv.y += ve * w1.y; Bv.z += ve * w1.z; Bv.w += ve * w1.w;
            }
            pb4[(o * U_ + u) * 2]     = A;
            pb4[(o * U_ + u) * 2 + 1] = Bv;
        }
        BARH();

        // ---- P6: c <- normalize_o( c * exp(x . wv) ) ----
        #pragma unroll
        for (int kk = 0; kk < 3; ++kk) {
            const int n = t + 512 * kk;
            if (n < N_) {
                const int u = n >> 5;
                const int q = xsw((h * N_ + n) * 2);
                const float4 x0 = xs4[q];
                const float4 x1 = xs4[q ^ 1];
                const float4* wvb = pb4 + u * 2;
                float* cp = cc + n;
                float tt[O_];
                float ss = 0.f;
                #pragma unroll
                for (int o = 0; o < O_; ++o) {
                    const float4 w0 = wvb[o * 72], w1 = wvb[o * 72 + 1];
                    const float d = x0.x * w0.x + x0.y * w0.y + x0.z * w0.z + x0.w * w0.w
                                  + x1.x * w1.x + x1.y * w1.y + x1.z * w1.z + x1.w * w1.w;
                    const float tv = cp[o * NP] * __expf(d);
                    tt[o] = tv;
                    ss += tv;
                }
                const float inv = 1.0f / ss;
                #pragma unroll
                for (int o = 0; o < O_; ++o) cp[o * NP] = tt[o] * inv;
            }
        }
        BARH();
    }

    // ---- write out[b0+h][o][e] ----
    if (t < O_ * E_) {
        out[(size_t)(b0 + h) * (O_ * E_) + t] = vv[t];
    }
#undef BARH
}

extern "C" void kernel_launch(void* const* d_in, const int* in_sizes, int n_in,
                              void* d_out, int out_size) {
    (void)in_sizes; (void)n_in; (void)out_size;
    const float* x = (const float*)d_in[0];
    const float* W = (const float*)d_in[1];
    float* out = (float*)d_out;

    const size_t smem = (size_t)SM_FLOATS * sizeof(float);  // 213,648 B
    cudaFuncSetAttribute(caps_route_kernel,
                         cudaFuncAttributeMaxDynamicSharedMemorySize, (int)smem);
    caps_route_kernel<<<B_ / BT, T_, smem>>>(x, W, out);
}

// round 8
// speedup vs baseline: 1.7134x; 1.7134x over previous
#include <cuda_runtime.h>

// CapsNet dynamic routing, factorized, BT=2 batches/CTA (structure of R5 with
// lane-linear W loads + warp-shuffle contractions in P3/P5, it0 specialization).

namespace {
constexpr int O_ = 10, U_ = 36, E_ = 16, F_ = 8;
constexpr int N_ = 1152;
constexpr int B_ = 256;
constexpr int BT = 2;
constexpr int T_ = 1024;             // 32 warps, 1 CTA/SM
constexpr int NP = 1157;             // c plane stride

// shared layout (floats)
constexpr int OFF_XS = 0;                        // swizzled x [BT][N][F]  18432
constexpr int OFF_C  = OFF_XS + BT * N_ * F_;    // c [BT][O][NP]          23140
constexpr int OFF_P  = OFF_C + BT * O_ * NP;     // pb 2880 float4         11520
constexpr int OFF_VV = OFF_P + 11520;            // [BT][O][E]               320
constexpr int SM_FLOATS = OFF_VV + BT * O_ * E_; // 53412 -> 213,648 B
} // namespace

__device__ __forceinline__ int xsw(int i) { return i ^ ((i >> 3) & 7); }

__global__ __launch_bounds__(T_, 1)
void caps_route_kernel(const float* __restrict__ x,
                       const float* __restrict__ Wg,
                       float* __restrict__ out) {
    extern __shared__ float sm[];
    float* cc  = sm + OFF_C;
    float* pbf = sm + OFF_P;
    float* vv  = sm + OFF_VV;
    float4* xs4 = reinterpret_cast<float4*>(sm + OFF_XS);
    float4* pb4 = reinterpret_cast<float4*>(pbf);

    const int tid = threadIdx.x;
    const int b0 = blockIdx.x * BT;
    const int warp = tid >> 5;
    const int lane = tid & 31;

    const float4* __restrict__ wp4 = reinterpret_cast<const float4*>(Wg);

    // ---- load x tiles (coalesced gmem read, swizzled smem store) ----
    {
        const float4* xg = reinterpret_cast<const float4*>(x) + (size_t)b0 * (N_ * F_ / 4);
        #pragma unroll
        for (int i = tid; i < BT * N_ * F_ / 4; i += T_) xs4[xsw(i)] = xg[i];
    }
    __syncthreads();

    // P2 task decode (576 tasks): tid = u<<4 | oh<<3 | fg<<2 | bb<<1 | sh
    const int p2_sh = tid & 1;
    const int p2_bb = (tid >> 1) & 1;
    const int p2_fg = (tid >> 2) & 1;
    const int p2_oh = (tid >> 3) & 1;
    const int p2_u  = tid >> 4;
    const float* p2_cb = cc + (p2_bb * 10 + p2_oh * 5) * NP + p2_u * 32 + p2_sh * 16;
    const int p2_pbase = (p2_bb * N_ + p2_u * 32 + p2_sh * 16) * 2 + p2_fg;
    float4* p2_pr = pb4 + tid * 5;

    // P3 decode: warp = o (<10); lane = e*2 + fh (lane-linear W)
    const int p3_e  = lane >> 1;
    const int p3_fh = lane & 1;

    // P5 decode: lane = e*2 + fg
    const int p5_e  = lane >> 1;
    const int sel1 = (lane >> 1) & 1;
    const int sel2 = (lane >> 2) & 1;
    const int p5_f = (lane & 1) * 4 + sel1 * 2 + sel2;

    for (int it = 0; it < 4; ++it) {
        // ---- P2: y partials for (bb,u,fg,oh,sh); 5 o-accumulators ----
        if (tid < 576) {
            if (it == 0) {
                float4 acc = make_float4(0.f, 0.f, 0.f, 0.f);
                #pragma unroll
                for (int j = 0; j < 16; ++j) {
                    const float4 xv = xs4[xsw(p2_pbase + 2 * j)];
                    acc.x += xv.x; acc.y += xv.y; acc.z += xv.z; acc.w += xv.w;
                }
                acc.x *= 0.1f; acc.y *= 0.1f; acc.z *= 0.1f; acc.w *= 0.1f;
                p2_pr[0] = acc; p2_pr[1] = acc; p2_pr[2] = acc; p2_pr[3] = acc; p2_pr[4] = acc;
            } else {
                float4 a0 = make_float4(0.f,0.f,0.f,0.f), a1 = a0, a2 = a0, a3 = a0, a4 = a0;
                #pragma unroll
                for (int j = 0; j < 16; ++j) {
                    const int s = (p2_u + j) & 15;          // rotation: spread banks
                    const float4 xv = xs4[xsw(p2_pbase + 2 * s)];
                    const float c0 = p2_cb[s];
                    const float c1 = p2_cb[NP + s];
                    const float c2 = p2_cb[2 * NP + s];
                    const float c3 = p2_cb[3 * NP + s];
                    const float c4 = p2_cb[4 * NP + s];
                    a0.x += c0 * xv.x; a0.y += c0 * xv.y; a0.z += c0 * xv.z; a0.w += c0 * xv.w;
                    a1.x += c1 * xv.x; a1.y += c1 * xv.y; a1.z += c1 * xv.z; a1.w += c1 * xv.w;
                    a2.x += c2 * xv.x; a2.y += c2 * xv.y; a2.z += c2 * xv.z; a2.w += c2 * xv.w;
                    a3.x += c3 * xv.x; a3.y += c3 * xv.y; a3.z += c3 * xv.z; a3.w += c3 * xv.w;
                    a4.x += c4 * xv.x; a4.y += c4 * xv.y; a4.z += c4 * xv.z; a4.w += c4 * xv.w;
                }
                p2_pr[0] = a0; p2_pr[1] = a1; p2_pr[2] = a2; p2_pr[3] = a3; p2_pr[4] = a4;
            }
        }
        __syncthreads();

        // ---- P3 (+fused squash): warp=o, lane=(e,fh); both bb share W reads ----
        if (warp < 10) {
            const int o = warp;
            const int oh = (o >= 5);
            const int k = o - 5 * oh;
            float p0 = 0.f, p1 = 0.f;
            #pragma unroll 6
            for (int u = 0; u < 36; ++u) {
                const float4 w = wp4[(o * 36 + u) * 32 + lane];   // contiguous 512B/warp
                const int pbase = ((u << 4) | (oh << 3) | (p3_fh << 2)) * 5 + k;
                float4 A  = pb4[pbase];            // bb0 sh0
                const float4 tA = pb4[pbase + 5];  // bb0 sh1
                float4 Bv = pb4[pbase + 10];       // bb1 sh0
                const float4 tB = pb4[pbase + 15]; // bb1 sh1
                A.x += tA.x; A.y += tA.y; A.z += tA.z; A.w += tA.w;
                Bv.x += tB.x; Bv.y += tB.y; Bv.z += tB.z; Bv.w += tB.w;
                p0 += w.x * A.x + w.y * A.y + w.z * A.z + w.w * A.w;
                p1 += w.x * Bv.x + w.y * Bv.y + w.z * Bv.z + w.w * Bv.w;
            }
            // merge fh halves (xor 1): full s[bb,o,e] in every lane pair
            const float s0 = p0 + __shfl_xor_sync(0xffffffffu, p0, 1);
            const float s1 = p1 + __shfl_xor_sync(0xffffffffu, p1, 1);
            float nsq0 = s0 * s0, nsq1 = s1 * s1;
            #pragma unroll
            for (int m = 2; m <= 16; m <<= 1) {
                nsq0 += __shfl_xor_sync(0xffffffffu, nsq0, m);
                nsq1 += __shfl_xor_sync(0xffffffffu, nsq1, m);
            }
            if (p3_fh == 0) vv[o * 16 + p3_e] = s0 * (sqrtf(nsq0) / (1.f + nsq0));
            else            vv[160 + o * 16 + p3_e] = s1 * (sqrtf(nsq1) / (1.f + nsq1));
        }
        __syncthreads();

        if (it == 3) break;

        // ---- P5: wv[bb,o,u,f]; warp per (o,u), lane-linear W, shuffle-reduce e ----
        for (int task = warp; task < 360; task += 32) {
            const float4 w = wp4[task * 32 + lane];   // contiguous 512B/warp
            const int o = task / 36;
            const float ve0 = vv[o * 16 + p5_e];
            const float ve1 = vv[160 + o * 16 + p5_e];
            float P0[4] = {w.x * ve0, w.y * ve0, w.z * ve0, w.w * ve0};
            float P1[4] = {w.x * ve1, w.y * ve1, w.z * ve1, w.w * ve1};
            // step 1 (xor 2): payload 4 -> 2  (keep payload[2*sel1+k], send other half)
            float k0a = P0[2 * sel1]     + __shfl_xor_sync(0xffffffffu, P0[2 * (sel1 ^ 1)],     2);
            float k0b = P0[2 * sel1 + 1] + __shfl_xor_sync(0xffffffffu, P0[2 * (sel1 ^ 1) + 1], 2);
            float k1a = P1[2 * sel1]     + __shfl_xor_sync(0xffffffffu, P1[2 * (sel1 ^ 1)],     2);
            float k1b = P1[2 * sel1 + 1] + __shfl_xor_sync(0xffffffffu, P1[2 * (sel1 ^ 1) + 1], 2);
            // step 2 (xor 4): payload 2 -> 1
            float r0 = (sel2 ? k0b : k0a) + __shfl_xor_sync(0xffffffffu, (sel2 ? k0a : k0b), 4);
            float r1 = (sel2 ? k1b : k1a) + __shfl_xor_sync(0xffffffffu, (sel2 ? k1a : k1b), 4);
            // steps 3,4 (xor 8, 16): plain adds
            r0 += __shfl_xor_sync(0xffffffffu, r0, 8);
            r1 += __shfl_xor_sync(0xffffffffu, r1, 8);
            r0 += __shfl_xor_sync(0xffffffffu, r0, 16);
            r1 += __shfl_xor_sync(0xffffffffu, r1, 16);
            if (lane < 8) {
                pbf[task * 8 + p5_f] = r0;
                pbf[2880 + task * 8 + p5_f] = r1;
            }
        }
        __syncthreads();

        // ---- P6: c <- normalize_o( c * exp(x . wv) ) ----
        #pragma unroll
        for (int kk = 0; kk < 3; ++kk) {
            const int idx = tid + T_ * kk;
            if (idx < BT * N_) {
                const int bb = (idx >= N_);
                const int n = idx - bb * N_;
                const int u = n >> 5;
                const int q = xsw((bb * N_ + n) * 2);
                const float4 x0 = xs4[q];
                const float4 x1 = xs4[q ^ 1];
                const float4* wvb = pb4 + bb * 720 + u * 2;
                float* cp = cc + (bb * 10) * NP + n;
                float t[O_];
                float ss = 0.f;
                if (it == 0) {
                    #pragma unroll
                    for (int o = 0; o < O_; ++o) {
                        const float4 w0 = wvb[o * 72], w1 = wvb[o * 72 + 1];
                        const float d = x0.x * w0.x + x0.y * w0.y + x0.z * w0.z + x0.w * w0.w
                                      + x1.x * w1.x + x1.y * w1.y + x1.z * w1.z + x1.w * w1.w;
                        const float tv = 0.1f * __expf(d);
                        t[o] = tv;
                        ss += tv;
                    }
                } else {
                    #pragma unroll
                    for (int o = 0; o < O_; ++o) {
                        const float4 w0 = wvb[o * 72], w1 = wvb[o * 72 + 1];
                        const float d = x0.x * w0.x + x0.y * w0.y + x0.z * w0.z + x0.w * w0.w
                                      + x1.x * w1.x + x1.y * w1.y + x1.z * w1.z + x1.w * w1.w;
                        const float tv = cp[o * NP] * __expf(d);
                        t[o] = tv;
                        ss += tv;
                    }
                }
                const float inv = 1.0f / ss;
                #pragma unroll
                for (int o = 0; o < O_; ++o) cp[o * NP] = t[o] * inv;
            }
        }
        __syncthreads();
    }

    // ---- write out[b][o][e] ----
    if (tid < BT * O_ * E_) {
        const int bb = tid / (O_ * E_);
        out[(size_t)(b0 + bb) * (O_ * E_) + (tid - bb * O_ * E_)] = vv[tid];
    }
}

extern "C" void kernel_launch(void* const* d_in, const int* in_sizes, int n_in,
                              void* d_out, int out_size) {
    (void)in_sizes; (void)n_in; (void)out_size;
    const float* x = (const float*)d_in[0];
    const float* W = (const float*)d_in[1];
    float* out = (float*)d_out;

    const size_t smem = (size_t)SM_FLOATS * sizeof(float);  // 213,648 B
    cudaFuncSetAttribute(caps_route_kernel,
                         cudaFuncAttributeMaxDynamicSharedMemorySize, (int)smem);
    caps_route_kernel<<<B_ / BT, T_, smem>>>(x, W, out);
}

// round 10
// speedup vs baseline: 1.9667x; 1.1479x over previous
#include <cuda_runtime.h>

// CapsNet dynamic routing, factorized. BT=1 batch per CTA, T=512, 2 CTAs/SM
// (co-resident CTAs hide each other's barriers and phase tails).
// Lane-linear W loads + warp-shuffle contractions, it0 specialization.
// R9 fix: OFF_P rounded up to a multiple of 4 floats (float4 alignment).

namespace {
constexpr int O_ = 10, U_ = 36, E_ = 16, F_ = 8;
constexpr int N_ = 1152;
constexpr int B_ = 256;
constexpr int T_ = 512;              // 16 warps, 2 CTAs/SM
constexpr int NP = 1157;             // c plane stride

// shared layout (floats)
constexpr int OFF_XS = 0;                    // swizzled x [N][F]       9216
constexpr int OFF_C  = OFF_XS + N_ * F_;     // c [O][NP]              11570
constexpr int OFF_P  = (OFF_C + O_ * NP + 3) & ~3;  // pb 1440 float4 (16B-aligned)
constexpr int OFF_VV = OFF_P + 5760;         // [O][E]                   160
constexpr int SM_FLOATS = OFF_VV + 160;      // -> 106,832 B
} // namespace

__device__ __forceinline__ int xsw(int i) { return i ^ ((i >> 3) & 7); }

__global__ __launch_bounds__(T_, 2)
void caps_route_kernel(const float* __restrict__ x,
                       const float* __restrict__ Wg,
                       float* __restrict__ out) {
    extern __shared__ float sm[];
    float* cc  = sm + OFF_C;
    float* pbf = sm + OFF_P;
    float* vv  = sm + OFF_VV;
    float4* xs4 = reinterpret_cast<float4*>(sm + OFF_XS);
    float4* pb4 = reinterpret_cast<float4*>(pbf);

    const int tid = threadIdx.x;
    const int b = blockIdx.x;
    const int warp = tid >> 5;
    const int lane = tid & 31;

    const float4* __restrict__ wp4 = reinterpret_cast<const float4*>(Wg);

    // ---- load x tile (coalesced gmem read, swizzled smem store) ----
    {
        const float4* xg = reinterpret_cast<const float4*>(x) + (size_t)b * (N_ * F_ / 4);
        #pragma unroll
        for (int i = tid; i < N_ * F_ / 4; i += T_) xs4[xsw(i)] = xg[i];
    }
    __syncthreads();

    // P2 task decode (288 tasks): tid = u<<3 | oh<<2 | fg<<1 | sh
    const int p2_sh = tid & 1;
    const int p2_fg = (tid >> 1) & 1;
    const int p2_oh = (tid >> 2) & 1;
    const int p2_u  = tid >> 3;
    const float* p2_cb = cc + p2_oh * 5 * NP + p2_u * 32 + p2_sh * 16;
    const int p2_pbase = (p2_u * 32 + p2_sh * 16) * 2 + p2_fg;
    float4* p2_pr = pb4 + tid * 5;

    // P3 decode: warp = o (<10); lane = e*2 + fh (lane-linear W)
    const int p3_e  = lane >> 1;
    const int p3_fh = lane & 1;

    // P5 decode: lane = e*2 + fh
    const int p5_e  = lane >> 1;
    const int sel1 = (lane >> 1) & 1;
    const int sel2 = (lane >> 2) & 1;
    const int p5_f = (lane & 1) * 4 + sel1 * 2 + sel2;

    for (int it = 0; it < 4; ++it) {
        // ---- P2: y partials for (u,fg,oh,sh); 5 o-accumulators ----
        if (tid < 288) {
            if (it == 0) {
                float4 acc = make_float4(0.f, 0.f, 0.f, 0.f);
                #pragma unroll
                for (int j = 0; j < 16; ++j) {
                    const float4 xv = xs4[xsw(p2_pbase + 2 * j)];
                    acc.x += xv.x; acc.y += xv.y; acc.z += xv.z; acc.w += xv.w;
                }
                acc.x *= 0.1f; acc.y *= 0.1f; acc.z *= 0.1f; acc.w *= 0.1f;
                p2_pr[0] = acc; p2_pr[1] = acc; p2_pr[2] = acc; p2_pr[3] = acc; p2_pr[4] = acc;
            } else {
                float4 a0 = make_float4(0.f,0.f,0.f,0.f), a1 = a0, a2 = a0, a3 = a0, a4 = a0;
                #pragma unroll
                for (int j = 0; j < 16; ++j) {
                    const int s = (p2_u + j) & 15;          // rotation: spread banks
                    const float4 xv = xs4[xsw(p2_pbase + 2 * s)];
                    const float c0 = p2_cb[s];
                    const float c1 = p2_cb[NP + s];
                    const float c2 = p2_cb[2 * NP + s];
                    const float c3 = p2_cb[3 * NP + s];
                    const float c4 = p2_cb[4 * NP + s];
                    a0.x += c0 * xv.x; a0.y += c0 * xv.y; a0.z += c0 * xv.z; a0.w += c0 * xv.w;
                    a1.x += c1 * xv.x; a1.y += c1 * xv.y; a1.z += c1 * xv.z; a1.w += c1 * xv.w;
                    a2.x += c2 * xv.x; a2.y += c2 * xv.y; a2.z += c2 * xv.z; a2.w += c2 * xv.w;
                    a3.x += c3 * xv.x; a3.y += c3 * xv.y; a3.z += c3 * xv.z; a3.w += c3 * xv.w;
                    a4.x += c4 * xv.x; a4.y += c4 * xv.y; a4.z += c4 * xv.z; a4.w += c4 * xv.w;
                }
                p2_pr[0] = a0; p2_pr[1] = a1; p2_pr[2] = a2; p2_pr[3] = a3; p2_pr[4] = a4;
            }
        }
        __syncthreads();

        // ---- P3 (+fused squash): warp=o, lane=(e,fh), lane-linear W ----
        if (warp < 10) {
            const int o = warp;
            const int oh = (o >= 5);
            const int k = o - 5 * oh;
            float p0 = 0.f;
            #pragma unroll 6
            for (int u = 0; u < 36; ++u) {
                const float4 w = wp4[(o * 36 + u) * 32 + lane];   // contiguous 512B/warp
                const int pbase = ((u << 3) | (oh << 2) | (p3_fh << 1)) * 5 + k;
                float4 A  = pb4[pbase];            // sh0
                const float4 tA = pb4[pbase + 5];  // sh1
                A.x += tA.x; A.y += tA.y; A.z += tA.z; A.w += tA.w;
                p0 += w.x * A.x + w.y * A.y + w.z * A.z + w.w * A.w;
            }
            // merge fh halves (xor 1): full s[o,e] in every lane pair
            const float s0 = p0 + __shfl_xor_sync(0xffffffffu, p0, 1);
            float nsq0 = s0 * s0;
            #pragma unroll
            for (int m = 2; m <= 16; m <<= 1)
                nsq0 += __shfl_xor_sync(0xffffffffu, nsq0, m);
            if (p3_fh == 0) vv[o * 16 + p3_e] = s0 * (sqrtf(nsq0) / (1.f + nsq0));
        }
        __syncthreads();

        if (it == 3) break;

        // ---- P5: wv[o,u,f]; warp per (o,u), lane-linear W, shuffle-reduce e ----
        for (int task = warp; task < 360; task += 16) {
            const float4 w = wp4[task * 32 + lane];   // contiguous 512B/warp
            const int o = task / 36;
            const float ve0 = vv[o * 16 + p5_e];
            float P0[4] = {w.x * ve0, w.y * ve0, w.z * ve0, w.w * ve0};
            // step 1 (xor 2): payload 4 -> 2
            float k0a = P0[2 * sel1]     + __shfl_xor_sync(0xffffffffu, P0[2 * (sel1 ^ 1)],     2);
            float k0b = P0[2 * sel1 + 1] + __shfl_xor_sync(0xffffffffu, P0[2 * (sel1 ^ 1) + 1], 2);
            // step 2 (xor 4): payload 2 -> 1
            float r0 = (sel2 ? k0b : k0a) + __shfl_xor_sync(0xffffffffu, (sel2 ? k0a : k0b), 4);
            // steps 3,4 (xor 8, 16)
            r0 += __shfl_xor_sync(0xffffffffu, r0, 8);
            r0 += __shfl_xor_sync(0xffffffffu, r0, 16);
            if (lane < 8) pbf[task * 8 + p5_f] = r0;
        }
        __syncthreads();

        // ---- P6: c <- normalize_o( c * exp(x . wv) ) ----
        #pragma unroll
        for (int kk = 0; kk < 3; ++kk) {
            const int n = tid + T_ * kk;
            if (n < N_) {
                const int u = n >> 5;
                const int q = xsw(n * 2);
                const float4 x0 = xs4[q];
                const float4 x1 = xs4[q ^ 1];
                const float4* wvb = pb4 + u * 2;
                float* cp = cc + n;
                float t[O_];
                float ss = 0.f;
                if (it == 0) {
                    #pragma unroll
                    for (int o = 0; o < O_; ++o) {
                        const float4 w0 = wvb[o * 72], w1 = wvb[o * 72 + 1];
                        const float d = x0.x * w0.x + x0.y * w0.y + x0.z * w0.z + x0.w * w0.w
                                      + x1.x * w1.x + x1.y * w1.y + x1.z * w1.z + x1.w * w1.w;
                        const float tv = 0.1f * __expf(d);
                        t[o] = tv;
                        ss += tv;
                    }
                } else {
                    #pragma unroll
                    for (int o = 0; o < O_; ++o) {
                        const float4 w0 = wvb[o * 72], w1 = wvb[o * 72 + 1];
                        const float d = x0.x * w0.x + x0.y * w0.y + x0.z * w0.z + x0.w * w0.w
                                      + x1.x * w1.x + x1.y * w1.y + x1.z * w1.z + x1.w * w1.w;
                        const float tv = cp[o * NP] * __expf(d);
                        t[o] = tv;
                        ss += tv;
                    }
                }
                const float inv = 1.0f / ss;
                #pragma unroll
                for (int o = 0; o < O_; ++o) cp[o * NP] = t[o] * inv;
            }
        }
        __syncthreads();
    }

    // ---- write out[b][o][e] ----
    if (tid < O_ * E_) {
        out[(size_t)b * (O_ * E_) + tid] = vv[tid];
    }
}

extern "C" void kernel_launch(void* const* d_in, const int* in_sizes, int n_in,
                              void* d_out, int out_size) {
    (void)in_sizes; (void)n_in; (void)out_size;
    const float* x = (const float*)d_in[0];
    const float* W = (const float*)d_in[1];
    float* out = (float*)d_out;

    const size_t smem = (size_t)SM_FLOATS * sizeof(float);  // 106,832 B
    cudaFuncSetAttribute(caps_route_kernel,
                         cudaFuncAttributeMaxDynamicSharedMemorySize, (int)smem);
    caps_route_kernel<<<B_, T_, smem>>>(x, W, out);
}

// round 11
// speedup vs baseline: 2.0660x; 1.0505x over previous
#include <cuda_runtime.h>

// CapsNet dynamic routing, factorized. 1 batch per CTA, T=512, 2 CTAs/SM.
// R11: P2 pre-reduces the sh halves via shfl (sh = lane bit 0), halving pb and
// halving P3's shared loads + dropping its merge adds.

namespace {
constexpr int O_ = 10, U_ = 36, E_ = 16, F_ = 8;
constexpr int N_ = 1152;
constexpr int B_ = 256;
constexpr int T_ = 512;              // 16 warps, 2 CTAs/SM
constexpr int NP = 1157;             // c plane stride

// shared layout (floats)
constexpr int OFF_XS = 0;                    // swizzled x [N][F]       9216
constexpr int OFF_C  = OFF_XS + N_ * F_;     // c [O][NP]              11570
constexpr int OFF_P  = (OFF_C + O_ * NP + 3) & ~3;  // pb 720 float4 (16B-aligned)
constexpr int OFF_VV = OFF_P + 2880;         // [O][E]                   160
constexpr int SM_FLOATS = OFF_VV + 160;      // -> 95,312 B
} // namespace

__device__ __forceinline__ int xsw(int i) { return i ^ ((i >> 3) & 7); }

__global__ __launch_bounds__(T_, 2)
void caps_route_kernel(const float* __restrict__ x,
                       const float* __restrict__ Wg,
                       float* __restrict__ out) {
    extern __shared__ float sm[];
    float* cc  = sm + OFF_C;
    float* pbf = sm + OFF_P;
    float* vv  = sm + OFF_VV;
    float4* xs4 = reinterpret_cast<float4*>(sm + OFF_XS);
    float4* pb4 = reinterpret_cast<float4*>(pbf);

    const int tid = threadIdx.x;
    const int b = blockIdx.x;
    const int warp = tid >> 5;
    const int lane = tid & 31;

    const float4* __restrict__ wp4 = reinterpret_cast<const float4*>(Wg);

    // ---- load x tile (coalesced gmem read, swizzled smem store) ----
    {
        const float4* xg = reinterpret_cast<const float4*>(x) + (size_t)b * (N_ * F_ / 4);
        #pragma unroll
        for (int i = tid; i < N_ * F_ / 4; i += T_) xs4[xsw(i)] = xg[i];
    }
    __syncthreads();

    // P2 task decode (288 tasks): tid = u<<3 | oh<<2 | fg<<1 | sh  (sh = lane bit 0)
    const int p2_sh = tid & 1;
    const int p2_fg = (tid >> 1) & 1;
    const int p2_oh = (tid >> 2) & 1;
    const int p2_u  = tid >> 3;
    const float* p2_cb = cc + p2_oh * 5 * NP + p2_u * 32 + p2_sh * 16;
    const int p2_pbase = (p2_u * 32 + p2_sh * 16) * 2 + p2_fg;
    float4* p2_pr = pb4 + (tid >> 1) * 5;    // task' = (u,oh,fg), sh reduced away

    // P3 decode: warp = o (<10); lane = e*2 + fh (lane-linear W)
    const int p3_e  = lane >> 1;
    const int p3_fh = lane & 1;

    // P5 decode
    const int p5_e  = lane >> 1;
    const int sel1 = (lane >> 1) & 1;
    const int sel2 = (lane >> 2) & 1;
    const int p5_f = (lane & 1) * 4 + sel1 * 2 + sel2;

    for (int it = 0; it < 4; ++it) {
        // ---- P2: y partials for (u,fg,oh); sh halves merged via shfl ----
        if (tid < 288) {
            float4 a0 = make_float4(0.f,0.f,0.f,0.f), a1 = a0, a2 = a0, a3 = a0, a4 = a0;
            if (it == 0) {
                #pragma unroll
                for (int j = 0; j < 16; ++j) {
                    const float4 xv = xs4[xsw(p2_pbase + 2 * j)];
                    a0.x += xv.x; a0.y += xv.y; a0.z += xv.z; a0.w += xv.w;
                }
                a0.x *= 0.1f; a0.y *= 0.1f; a0.z *= 0.1f; a0.w *= 0.1f;
                a1 = a0; a2 = a0; a3 = a0; a4 = a0;
            } else {
                #pragma unroll
                for (int j = 0; j < 16; ++j) {
                    const int s = (p2_u + j) & 15;          // rotation: spread banks
                    const float4 xv = xs4[xsw(p2_pbase + 2 * s)];
                    const float c0 = p2_cb[s];
                    const float c1 = p2_cb[NP + s];
                    const float c2 = p2_cb[2 * NP + s];
                    const float c3 = p2_cb[3 * NP + s];
                    const float c4 = p2_cb[4 * NP + s];
                    a0.x += c0 * xv.x; a0.y += c0 * xv.y; a0.z += c0 * xv.z; a0.w += c0 * xv.w;
                    a1.x += c1 * xv.x; a1.y += c1 * xv.y; a1.z += c1 * xv.z; a1.w += c1 * xv.w;
                    a2.x += c2 * xv.x; a2.y += c2 * xv.y; a2.z += c2 * xv.z; a2.w += c2 * xv.w;
                    a3.x += c3 * xv.x; a3.y += c3 * xv.y; a3.z += c3 * xv.z; a3.w += c3 * xv.w;
                    a4.x += c4 * xv.x; a4.y += c4 * xv.y; a4.z += c4 * xv.z; a4.w += c4 * xv.w;
                }
            }
            // merge sh halves (lane bit 0)
            a0.x += __shfl_xor_sync(0xffffffffu, a0.x, 1);
            a0.y += __shfl_xor_sync(0xffffffffu, a0.y, 1);
            a0.z += __shfl_xor_sync(0xffffffffu, a0.z, 1);
            a0.w += __shfl_xor_sync(0xffffffffu, a0.w, 1);
            a1.x += __shfl_xor_sync(0xffffffffu, a1.x, 1);
            a1.y += __shfl_xor_sync(0xffffffffu, a1.y, 1);
            a1.z += __shfl_xor_sync(0xffffffffu, a1.z, 1);
            a1.w += __shfl_xor_sync(0xffffffffu, a1.w, 1);
            a2.x += __shfl_xor_sync(0xffffffffu, a2.x, 1);
            a2.y += __shfl_xor_sync(0xffffffffu, a2.y, 1);
            a2.z += __shfl_xor_sync(0xffffffffu, a2.z, 1);
            a2.w += __shfl_xor_sync(0xffffffffu, a2.w, 1);
            a3.x += __shfl_xor_sync(0xffffffffu, a3.x, 1);
            a3.y += __shfl_xor_sync(0xffffffffu, a3.y, 1);
            a3.z += __shfl_xor_sync(0xffffffffu, a3.z, 1);
            a3.w += __shfl_xor_sync(0xffffffffu, a3.w, 1);
            a4.x += __shfl_xor_sync(0xffffffffu, a4.x, 1);
            a4.y += __shfl_xor_sync(0xffffffffu, a4.y, 1);
            a4.z += __shfl_xor_sync(0xffffffffu, a4.z, 1);
            a4.w += __shfl_xor_sync(0xffffffffu, a4.w, 1);
            if (p2_sh == 0) {
                p2_pr[0] = a0; p2_pr[1] = a1; p2_pr[2] = a2; p2_pr[3] = a3; p2_pr[4] = a4;
            }
        }
        __syncthreads();

        // ---- P3 (+fused squash): warp=o, lane=(e,fh), lane-linear W ----
        if (warp < 10) {
            const int o = warp;
            const int oh = (o >= 5);
            const int k = o - 5 * oh;
            const int rbase = (oh * 2 + p3_fh) * 5 + k;   // (u,oh,fg=fh) row, k-th f4
            float p0 = 0.f;
            #pragma unroll 6
            for (int u = 0; u < 36; ++u) {
                const float4 w = wp4[(o * 36 + u) * 32 + lane];   // contiguous 512B/warp
                const float4 A = pb4[u * 20 + rbase];
                p0 += w.x * A.x + w.y * A.y + w.z * A.z + w.w * A.w;
            }
            // merge fh halves (xor 1): full s[o,e] in every lane pair
            const float s0 = p0 + __shfl_xor_sync(0xffffffffu, p0, 1);
            float nsq0 = s0 * s0;
            #pragma unroll
            for (int m = 2; m <= 16; m <<= 1)
                nsq0 += __shfl_xor_sync(0xffffffffu, nsq0, m);
            if (p3_fh == 0) vv[o * 16 + p3_e] = s0 * (sqrtf(nsq0) / (1.f + nsq0));
        }
        __syncthreads();

        if (it == 3) break;

        // ---- P5: wv[o,u,f]; warp per (o,u), lane-linear W, shuffle-reduce e ----
        for (int task = warp; task < 360; task += 16) {
            const float4 w = wp4[task * 32 + lane];   // contiguous 512B/warp
            const int o = task / 36;
            const float ve0 = vv[o * 16 + p5_e];
            float P0[4] = {w.x * ve0, w.y * ve0, w.z * ve0, w.w * ve0};
            // step 1 (xor 2): payload 4 -> 2
            float k0a = P0[2 * sel1]     + __shfl_xor_sync(0xffffffffu, P0[2 * (sel1 ^ 1)],     2);
            float k0b = P0[2 * sel1 + 1] + __shfl_xor_sync(0xffffffffu, P0[2 * (sel1 ^ 1) + 1], 2);
            // step 2 (xor 4): payload 2 -> 1
            float r0 = (sel2 ? k0b : k0a) + __shfl_xor_sync(0xffffffffu, (sel2 ? k0a : k0b), 4);
            // steps 3,4 (xor 8, 16)
            r0 += __shfl_xor_sync(0xffffffffu, r0, 8);
            r0 += __shfl_xor_sync(0xffffffffu, r0, 16);
            if (lane < 8) pbf[task * 8 + p5_f] = r0;
        }
        __syncthreads();

        // ---- P6: c <- normalize_o( c * exp(x . wv) ) ----
        #pragma unroll
        for (int kk = 0; kk < 3; ++kk) {
            const int n = tid + T_ * kk;
            if (n < N_) {
                const int u = n >> 5;
                const int q = xsw(n * 2);
                const float4 x0 = xs4[q];
                const float4 x1 = xs4[q ^ 1];
                const float4* wvb = pb4 + u * 2;
                float* cp = cc + n;
                float t[O_];
                float ss = 0.f;
                if (it == 0) {
                    #pragma unroll
                    for (int o = 0; o < O_; ++o) {
                        const float4 w0 = wvb[o * 72], w1 = wvb[o * 72 + 1];
                        const float d = x0.x * w0.x + x0.y * w0.y + x0.z * w0.z + x0.w * w0.w
                                      + x1.x * w1.x + x1.y * w1.y + x1.z * w1.z + x1.w * w1.w;
                        const float tv = 0.1f * __expf(d);
                        t[o] = tv;
                        ss += tv;
                    }
                } else {
                    #pragma unroll
                    for (int o = 0; o < O_; ++o) {
                        const float4 w0 = wvb[o * 72], w1 = wvb[o * 72 + 1];
                        const float d = x0.x * w0.x + x0.y * w0.y + x0.z * w0.z + x0.w * w0.w
                                      + x1.x * w1.x + x1.y * w1.y + x1.z * w1.z + x1.w * w1.w;
                        const float tv = cp[o * NP] * __expf(d);
                        t[o] = tv;
                        ss += tv;
                    }
                }
                const float inv = 1.0f / ss;
                #pragma unroll
                for (int o = 0; o < O_; ++o) cp[o * NP] = t[o] * inv;
            }
        }
        __syncthreads();
    }

    // ---- write out[b][o][e] ----
    if (tid < O_ * E_) {
        out[(size_t)b * (O_ * E_) + tid] = vv[tid];
    }
}

extern "C" void kernel_launch(void* const* d_in, const int* in_sizes, int n_in,
                              void* d_out, int out_size) {
    (void)in_sizes; (void)n_in; (void)out_size;
    const float* x = (const float*)d_in[0];
    const float* W = (const float*)d_in[1];
    float* out = (float*)d_out;

    const size_t smem = (size_t)SM_FLOATS * sizeof(float);  // 95,312 B
    cudaFuncSetAttribute(caps_route_kernel,
                         cudaFuncAttributeMaxDynamicSharedMemorySize, (int)smem);
    caps_route_kernel<<<B_, T_, smem>>>(x, W, out);
}